// round 11
// baseline (speedup 1.0000x reference)
#include <cuda_runtime.h>
#include <cstdint>

#define BB 64
#define TT 512
#define DD 256
#define UU 512
#define NCTA 128
#define NTH 288           // 8 compute warps + 1 poller warp
#define WROW 520          // weight row stride (floats): col rows 8 banks apart
#define REDO 52           // reduction out-stride (floats), 16B-aligned, padded

// dynamic smem layout for lstm kernel
#define H_BYTES  (64 * 2048)                     // h staging [64][512] f32, swizzled
#define W_OFF    H_BYTES                         // 131072
#define W_BYTES  (3 * 4 * WROW * 4)              // 24960
#define R_OFF    (W_OFF + W_BYTES)               // 156032
#define R_BYTES  (256 * REDO * 4)                // 53248
#define FLAG_OFF (R_OFF + R_BYTES)               // 209280
#define SM_TOTAL (FLAG_OFF + 16)                 // 209296

// Scratch (static device arrays; no cudaMalloc anywhere).
__device__ float g_xp[3][TT][BB][UU];      // input projections [g][t][b][u]
__device__ float g_hbuf[2][BB * UU];       // ping-pong hidden state (fp32)
__device__ __align__(128) unsigned g_arrive[NCTA];  // per-CTA arrival slots

// ---- packed f32x2 helpers (full-rate fp32 on sm_103a) ----
__device__ __forceinline__ void fma2(unsigned long long &d, unsigned long long a,
                                     unsigned long long b) {
    asm("fma.rn.f32x2 %0, %1, %2, %0;" : "+l"(d) : "l"(a), "l"(b));
}
__device__ __forceinline__ float2 upk(unsigned long long v) {
    float2 r;
    asm("mov.b64 {%0, %1}, %2;" : "=f"(r.x), "=f"(r.y) : "l"(v));
    return r;
}
__device__ __forceinline__ void cp16(uint32_t dst, const float* src) {
    asm volatile("cp.async.cg.shared.global [%0], [%1], 16;" :: "r"(dst), "l"(src));
}
__device__ __forceinline__ unsigned ldrelax(const unsigned* p) {
    unsigned v;
    asm volatile("ld.relaxed.gpu.global.u32 %0, [%1];" : "=r"(v) : "l"(p)
                 : "memory");
    return v;
}

__device__ __forceinline__ float fsig(float x) {
    return __fdividef(1.0f, 1.0f + __expf(-x));
}
__device__ __forceinline__ float ftanh(float x) {
    float e = __expf(-2.0f * fabsf(x));
    float r = __fdividef(1.0f - e, 1.0f + e);
    return copysignf(r, x);
}

// ============================================================================
// Phase 1: xp[g][t][b][u] = x[b,t,:] @ w_xg[:,u] + b_g[u]   (unchanged)
// ============================================================================
__global__ void __launch_bounds__(256, 2) proj_kernel(
    const float* __restrict__ x,
    const float* __restrict__ wxi, const float* __restrict__ wxf,
    const float* __restrict__ wxc,
    const float* __restrict__ bi, const float* __restrict__ bf,
    const float* __restrict__ bc) {
    __shared__ __align__(16) float xs[64][33];
    __shared__ __align__(16) float ws[3][32][64];

    const int tid = threadIdx.x;
    const int t = blockIdx.y;
    const int ub = blockIdx.x * 64;

    const int ug = tid & 15;
    const int bg = tid >> 4;
    const int ul = ug << 2;
    const int b0 = bg << 2;

    unsigned long long acc[3][4][2];
#pragma unroll
    for (int g = 0; g < 3; ++g)
#pragma unroll
        for (int i = 0; i < 4; ++i) { acc[g][i][0] = 0ull; acc[g][i][1] = 0ull; }

    for (int k0 = 0; k0 < DD; k0 += 32) {
#pragma unroll
        for (int i = 0; i < 8; ++i) {
            int idx = tid + i * 256;
            int bb = idx >> 5, kk = idx & 31;
            xs[bb][kk] = x[(bb * TT + t) * DD + k0 + kk];
        }
#pragma unroll
        for (int i = 0; i < 24; ++i) {
            int idx = tid + i * 256;
            int g = idx >> 11, r = idx & 2047, kk = r >> 6, uu = r & 63;
            const float* w = (g == 0) ? wxi : ((g == 1) ? wxf : wxc);
            ws[g][kk][uu] = w[(k0 + kk) * UU + ub + uu];
        }
        __syncthreads();
#pragma unroll
        for (int kk = 0; kk < 32; ++kk) {
            unsigned long long xb[4];
#pragma unroll
            for (int i = 0; i < 4; ++i) {
                unsigned xv = __float_as_uint(xs[b0 + i][kk]);
                asm("mov.b64 %0, {%1, %1};" : "=l"(xb[i]) : "r"(xv));
            }
#pragma unroll
            for (int g = 0; g < 3; ++g) {
                const ulonglong2 wv = *(const ulonglong2*)&ws[g][kk][ul];
#pragma unroll
                for (int i = 0; i < 4; ++i) {
                    fma2(acc[g][i][0], xb[i], wv.x);
                    fma2(acc[g][i][1], xb[i], wv.y);
                }
            }
        }
        __syncthreads();
    }

    const float* biases[3] = {bi, bf, bc};
#pragma unroll
    for (int g = 0; g < 3; ++g) {
        float2 bv0 = *(const float2*)&biases[g][ub + ul];
        float2 bv1 = *(const float2*)&biases[g][ub + ul + 2];
#pragma unroll
        for (int i = 0; i < 4; ++i) {
            float2 r0 = upk(acc[g][i][0]);
            float2 r1 = upk(acc[g][i][1]);
            r0.x += bv0.x; r0.y += bv0.y;
            r1.x += bv1.x; r1.y += bv1.y;
            float* dst = &g_xp[g][t][b0 + i][ub + ul];
            *(float2*)dst = r0;
            *(float2*)(dst + 2) = r1;
        }
    }
}

// ============================================================================
// Init: h0 -> g_hbuf[1]; reset arrival slots (graph-replay safe)
// ============================================================================
__global__ void init_kernel(const float* __restrict__ h0) {
    int i = blockIdx.x * blockDim.x + threadIdx.x;
    if (i < BB * UU) g_hbuf[1][i] = h0[i];
    if (i < NCTA) g_arrive[i] = 0u;
}

// ============================================================================
// Phase 2: persistent recurrent kernel. 128 CTAs x 288 threads.
// Warps 0..7 compute (R10 big-tile core, unchanged); warp 8 = barrier poller.
// Grid barrier (atomic-free): each CTA release-stores t+1 to its own slot in
// g_arrive[128]; poller lane L polls slots L, L+32, L+64, L+96 (relaxed,
// warp-coalesced), __all_sync ballot, fence.acq_rel.gpu on exit, then
// releases the CTA via an smem flag.
// ============================================================================
__global__ void __launch_bounds__(NTH, 1) lstm_kernel(
    const float* __restrict__ whi, const float* __restrict__ whf,
    const float* __restrict__ whc, const float* __restrict__ c0,
    float* __restrict__ out) {
    extern __shared__ __align__(16) char sm[];
    float* smW = (float*)(sm + W_OFF);
    float* smR = (float*)(sm + R_OFF);

    const int tid = threadIdx.x;
    const int wid = tid >> 5, lane = tid & 31;
    const int u0 = blockIdx.x * 4;
    // compute roles (tid < 256)
    const int c  = tid & 1;
    const int bg = (tid >> 1) & 7;
    const int ks = tid >> 4;                 // 0..15
    const int rot = (ks & 1) * 2;            // slot rotation for ks pairs
    // staging roles (warp-local)
    const int lr = lane >> 3, ls = lane & 7;
    // gate roles (tid < 256): output o = tid
    const int b2 = tid >> 2, c2 = tid & 3;
    const int u = u0 + c2;

    {
        const float* wsrc[3] = {whi, whf, whc};
        for (int i = tid; i < 3 * 4 * UU; i += NTH) {
            int cc = i & 3, k = (i >> 2) & 511, g = i >> 11;
            smW[(g * 4 + cc) * WROW + k] = wsrc[g][k * UU + u0 + cc];
        }
    }
    float cst = (tid < 256) ? c0[b2 * UU + u] : 0.0f;

    const uint32_t smbase = (uint32_t)__cvta_generic_to_shared(sm);
    const uint32_t flagaddr = smbase + FLAG_OFF;
    if (tid == 0) *(unsigned*)(sm + FLAG_OFF) = 0u;

    const int perm = bg * 2 + c;                       // ks-XOR bijection
    float* redw = smR + (bg * 8) * 4 * REDO + (c * 2) * REDO + (ks ^ perm);
    const float* redr = smR + tid * REDO;              // o = tid, 16B-aligned

    const size_t gstride = (size_t)TT * BB * UU;
    const float* xpi = &g_xp[0][0][0][0] + 0 * gstride + (size_t)b2 * UU + u;
    const float* xpf = &g_xp[0][0][0][0] + 1 * gstride + (size_t)b2 * UU + u;
    const float* xpc = &g_xp[0][0][0][0] + 2 * gstride + (size_t)b2 * UU + u;
    float* orow = out + (size_t)b2 * TT * UU + u;

    __syncthreads();

    for (int t = 0; t < TT; ++t) {
        if (tid < 256) {
            // prefetch xp(t) before the flag wait (independent of recurrence)
            float pi = __ldcg(xpi + (size_t)t * (BB * UU));
            float pf = __ldcg(xpf + (size_t)t * (BB * UU));
            float pc = __ldcg(xpc + (size_t)t * (BB * UU));

            if (t > 0) {
                unsigned v;
                do {
                    asm volatile("ld.acquire.cta.shared.u32 %0, [%1];"
                                 : "=r"(v) : "r"(flagaddr) : "memory");
                } while (v < (unsigned)t);
            }

            // stage THIS warp's h region: all 64 rows x slots [wid*16,+16)
            const float* hsrc = &g_hbuf[(t + 1) & 1][0];
#pragma unroll
            for (int j = 0; j < 32; ++j) {
                int jr = j & 15, js = j >> 4;
                int r = jr * 4 + lr;
                int s = wid * 16 + js * 8 + ls;
                uint32_t dst = smbase + r * 2048 +
                               (uint32_t)((s ^ ((r >> 3) & 7)) << 4);
                cp16(dst, hsrc + r * 512 + s * 4);
            }
            asm volatile("cp.async.commit_group;");
            asm volatile("cp.async.wait_group 0;");
            __syncwarp();

            unsigned long long acc[8][3][2];
#pragma unroll
            for (int i = 0; i < 8; ++i)
#pragma unroll
                for (int g = 0; g < 3; ++g) {
                    acc[i][g][0] = 0ull; acc[i][g][1] = 0ull;
                }

#pragma unroll
            for (int j = 0; j < 8; ++j) {
                const int k4 = ks * 8 + ((j + rot) & 7);
                ulonglong2 wv[3][2];
#pragma unroll
                for (int g = 0; g < 3; ++g)
#pragma unroll
                    for (int q = 0; q < 2; ++q)
                        wv[g][q] = *(const ulonglong2*)(
                            smW + (g * 4 + c * 2 + q) * WROW + k4 * 4);
                const uint32_t koff = (uint32_t)((k4 ^ bg) << 4);
                const char* hb = sm + (bg * 8) * 2048 + koff;
#pragma unroll
                for (int i = 0; i < 8; ++i) {
                    const ulonglong2 hv = *(const ulonglong2*)(hb + i * 2048);
#pragma unroll
                    for (int g = 0; g < 3; ++g) {
#pragma unroll
                        for (int q = 0; q < 2; ++q) {
                            fma2(acc[i][g][q], hv.x, wv[g][q].x);
                            fma2(acc[i][g][q], hv.y, wv[g][q].y);
                        }
                    }
                }
            }

            // partial writes
#pragma unroll
            for (int i = 0; i < 8; ++i)
#pragma unroll
                for (int g = 0; g < 3; ++g)
#pragma unroll
                    for (int q = 0; q < 2; ++q) {
                        float2 v = upk(acc[i][g][q]);
                        redw[i * 4 * REDO + q * REDO + g * 16] = v.x + v.y;
                    }
            __syncthreads();

            // reduce + gates: 16 contiguous partials per gate
            float s[3];
#pragma unroll
            for (int g = 0; g < 3; ++g) {
                const float* rb = redr + g * 16;
                float4 a = *(const float4*)(rb + 0);
                float4 b = *(const float4*)(rb + 4);
                float4 d = *(const float4*)(rb + 8);
                float4 e = *(const float4*)(rb + 12);
                s[g] = (((a.x + a.y) + (a.z + a.w)) + ((b.x + b.y) + (b.z + b.w)))
                     + (((d.x + d.y) + (d.z + d.w)) + ((e.x + e.y) + (e.z + e.w)));
            }
            float ig = fsig(pi + s[0]);
            float fg = fsig(pf + s[1]);
            float cin = ftanh(pc + s[2]);
            cst = fg * cst + ig * cin;
            float hn = ftanh(cst);
            __stcg(&g_hbuf[t & 1][b2 * UU + u], hn);
            orow[(size_t)t * UU] = hn;

            if (t < TT - 1) {
                asm volatile("membar.cta;" ::: "memory");
                asm volatile("bar.arrive 1, %0;" :: "n"(NTH) : "memory");
            }
        } else {
            __syncthreads();
            if (t < TT - 1) {
                asm volatile("bar.sync 1, %0;" :: "n"(NTH) : "memory");
                const unsigned tg = (unsigned)(t + 1);
                if (lane == 0) {
                    asm volatile("st.release.gpu.global.u32 [%0], %1;"
                                 :: "l"(&g_arrive[blockIdx.x]), "r"(tg)
                                 : "memory");
                }
                // parallel poll: lane L covers slots L, L+32, L+64, L+96
                bool ok;
                do {
                    unsigned v0 = ldrelax(&g_arrive[lane]);
                    unsigned v1 = ldrelax(&g_arrive[lane + 32]);
                    unsigned v2 = ldrelax(&g_arrive[lane + 64]);
                    unsigned v3 = ldrelax(&g_arrive[lane + 96]);
                    ok = (v0 >= tg) & (v1 >= tg) & (v2 >= tg) & (v3 >= tg);
                } while (!__all_sync(0xffffffffu, ok));
                asm volatile("fence.acq_rel.gpu;" ::: "memory");
                if (lane == 0) {
                    asm volatile("st.release.cta.shared.u32 [%0], %1;"
                                 :: "r"(flagaddr), "r"(tg) : "memory");
                }
                __syncwarp();
            }
        }
    }
}

extern "C" void kernel_launch(void* const* d_in, const int* in_sizes, int n_in,
                              void* d_out, int out_size) {
    const float* x   = (const float*)d_in[0];
    const float* wxi = (const float*)d_in[1];
    const float* wxf = (const float*)d_in[2];
    const float* wxc = (const float*)d_in[3];
    const float* whi = (const float*)d_in[4];
    const float* whf = (const float*)d_in[5];
    const float* whc = (const float*)d_in[6];
    const float* bi  = (const float*)d_in[7];
    const float* bf  = (const float*)d_in[8];
    const float* bc  = (const float*)d_in[9];
    const float* h0  = (const float*)d_in[10];
    const float* c0  = (const float*)d_in[11];
    float* out = (float*)d_out;

    cudaFuncSetAttribute(lstm_kernel, cudaFuncAttributeMaxDynamicSharedMemorySize,
                         SM_TOTAL);

    proj_kernel<<<dim3(8, TT), 256>>>(x, wxi, wxf, wxc, bi, bf, bc);
    init_kernel<<<(BB * UU + 255) / 256, 256>>>(h0);
    lstm_kernel<<<NCTA, NTH, SM_TOTAL>>>(whi, whf, whc, c0, out);
}

// round 12
// speedup vs baseline: 2.2335x; 2.2335x over previous
#include <cuda_runtime.h>
#include <cstdint>

#define BB 64
#define TT 512
#define DD 256
#define UU 512
#define NCTA 128

// ---------------- fallback (R10) config ----------------
#define NTH 288
#define WROW 520
#define REDO 52
#define H_BYTES  (64 * 2048)
#define W_OFF    H_BYTES
#define W_BYTES  (3 * 4 * WROW * 4)
#define R_OFF    (W_OFF + W_BYTES)
#define R_BYTES  (256 * REDO * 4)
#define FLAG_OFF (R_OFF + R_BYTES)
#define SM_TOTAL (FLAG_OFF + 16)

// ---------------- cluster config ----------------
#define CL 16
#define CW_BYTES (3 * 32 * 512 * 4)          // 196608 (swizzled weight slots)
#define CH_OFF   CW_BYTES
#define CH_BYTES (8 * 512 * 4)               // 16384 (full h for 8 rows)
#define CR_OFF   (CH_OFF + CH_BYTES)         // 212992
#define CR_BYTES (8 * 3 * 32 * 4)            // 3072
#define CSM_TOTAL (CR_OFF + CR_BYTES)        // 216064

// Scratch (static device arrays; no cudaMalloc anywhere).
__device__ float g_xp[3][TT][BB][UU];
__device__ float g_hbuf[2][BB * UU];
__device__ unsigned g_count;

__device__ __forceinline__ void fma2(unsigned long long &d, unsigned long long a,
                                     unsigned long long b) {
    asm("fma.rn.f32x2 %0, %1, %2, %0;" : "+l"(d) : "l"(a), "l"(b));
}
__device__ __forceinline__ float2 upk(unsigned long long v) {
    float2 r;
    asm("mov.b64 {%0, %1}, %2;" : "=f"(r.x), "=f"(r.y) : "l"(v));
    return r;
}
__device__ __forceinline__ void cp16(uint32_t dst, const float* src) {
    asm volatile("cp.async.cg.shared.global [%0], [%1], 16;" :: "r"(dst), "l"(src));
}
__device__ __forceinline__ float fsig(float x) {
    return __fdividef(1.0f, 1.0f + __expf(-x));
}
__device__ __forceinline__ float ftanh(float x) {
    float e = __expf(-2.0f * fabsf(x));
    float r = __fdividef(1.0f - e, 1.0f + e);
    return copysignf(r, x);
}

// ============================================================================
// Phase 1: xp[g][t][b][u] = x[b,t,:] @ w_xg[:,u] + b_g[u]   (unchanged)
// ============================================================================
__global__ void __launch_bounds__(256, 2) proj_kernel(
    const float* __restrict__ x,
    const float* __restrict__ wxi, const float* __restrict__ wxf,
    const float* __restrict__ wxc,
    const float* __restrict__ bi, const float* __restrict__ bf,
    const float* __restrict__ bc) {
    __shared__ __align__(16) float xs[64][33];
    __shared__ __align__(16) float ws[3][32][64];

    const int tid = threadIdx.x;
    const int t = blockIdx.y;
    const int ub = blockIdx.x * 64;

    const int ug = tid & 15;
    const int bg = tid >> 4;
    const int ul = ug << 2;
    const int b0 = bg << 2;

    unsigned long long acc[3][4][2];
#pragma unroll
    for (int g = 0; g < 3; ++g)
#pragma unroll
        for (int i = 0; i < 4; ++i) { acc[g][i][0] = 0ull; acc[g][i][1] = 0ull; }

    for (int k0 = 0; k0 < DD; k0 += 32) {
#pragma unroll
        for (int i = 0; i < 8; ++i) {
            int idx = tid + i * 256;
            int bb = idx >> 5, kk = idx & 31;
            xs[bb][kk] = x[(bb * TT + t) * DD + k0 + kk];
        }
#pragma unroll
        for (int i = 0; i < 24; ++i) {
            int idx = tid + i * 256;
            int g = idx >> 11, r = idx & 2047, kk = r >> 6, uu = r & 63;
            const float* w = (g == 0) ? wxi : ((g == 1) ? wxf : wxc);
            ws[g][kk][uu] = w[(k0 + kk) * UU + ub + uu];
        }
        __syncthreads();
#pragma unroll
        for (int kk = 0; kk < 32; ++kk) {
            unsigned long long xb[4];
#pragma unroll
            for (int i = 0; i < 4; ++i) {
                unsigned xv = __float_as_uint(xs[b0 + i][kk]);
                asm("mov.b64 %0, {%1, %1};" : "=l"(xb[i]) : "r"(xv));
            }
#pragma unroll
            for (int g = 0; g < 3; ++g) {
                const ulonglong2 wv = *(const ulonglong2*)&ws[g][kk][ul];
#pragma unroll
                for (int i = 0; i < 4; ++i) {
                    fma2(acc[g][i][0], xb[i], wv.x);
                    fma2(acc[g][i][1], xb[i], wv.y);
                }
            }
        }
        __syncthreads();
    }

    const float* biases[3] = {bi, bf, bc};
#pragma unroll
    for (int g = 0; g < 3; ++g) {
        float2 bv0 = *(const float2*)&biases[g][ub + ul];
        float2 bv1 = *(const float2*)&biases[g][ub + ul + 2];
#pragma unroll
        for (int i = 0; i < 4; ++i) {
            float2 r0 = upk(acc[g][i][0]);
            float2 r1 = upk(acc[g][i][1]);
            r0.x += bv0.x; r0.y += bv0.y;
            r1.x += bv1.x; r1.y += bv1.y;
            float* dst = &g_xp[g][t][b0 + i][ub + ul];
            *(float2*)dst = r0;
            *(float2*)(dst + 2) = r1;
        }
    }
}

// ============================================================================
// Init: h0 -> g_hbuf[1] (for fallback); reset g_count
// ============================================================================
__global__ void init_kernel(const float* __restrict__ h0) {
    int i = blockIdx.x * blockDim.x + threadIdx.x;
    if (i < BB * UU) g_hbuf[1][i] = h0[i];
    if (i == 0) g_count = 0u;
}

// ============================================================================
// CLUSTER kernel: 8 clusters x 16 CTAs; cluster owns 8 batch rows; rank owns
// 32 u-cols x 3 gates (weights smem-resident, slot-swizzled s^=(c&7)).
// Full h for 8 rows lives in EVERY CTA's smem (slot-swizzled s^=(b&7)).
// Thread (cgrp=tid>>5, c4=lane&3, ks=lane>>2): col c=cgrp*4+c4, k4=j*8+ks.
// Reduce over ks via shfl (lane stride 4). Gates: thread (b2=tid>>5,c2).
// h exchange: scatter h_new element to all 16 CTAs via mapa+st.shared::cluster.
// Sync: split cluster barriers A (reads done) and B (writes published).
// ============================================================================
__global__ void __launch_bounds__(256, 1)
lstm_cluster(const float* __restrict__ whi, const float* __restrict__ whf,
             const float* __restrict__ whc, const float* __restrict__ h0,
             const float* __restrict__ c0, float* __restrict__ out) {
    extern __shared__ __align__(16) char sm[];
    float* sred = (float*)(sm + CR_OFF);

    const int tid = threadIdx.x;
    const int lane = tid & 31;
    const int cgrp = tid >> 5;
    const int c4 = lane & 3, ks = lane >> 2;
    const int c = cgrp * 4 + c4;
    const int b2 = tid >> 5, c2 = tid & 31;
    uint32_t rank;
    asm("mov.u32 %0, %%cluster_ctarank;" : "=r"(rank));
    const int cid = blockIdx.x >> 4;
    const int u0 = (int)rank * 32;
    const int gb = cid * 8 + b2;

    // weights -> smem (swizzled 16B slots)
    for (int i = tid; i < 3 * 512 * 32; i += 256) {
        int cc = i & 31, k = (i >> 5) & 511, g = i >> 14;
        const float* wsrc = (g == 0) ? whi : ((g == 1) ? whf : whc);
        float v = wsrc[k * UU + u0 + cc];
        uint32_t off = (uint32_t)(((g * 32 + cc) * 128 + ((k >> 2) ^ (cc & 7))) * 16
                                  + (k & 3) * 4);
        *(float*)(sm + off) = v;
    }
    // h0 -> local full-h (swizzled)
    for (int it = 0; it < 16; ++it) {
        int uu = it * 32 + c2;
        int S = uu >> 2;
        *(float*)(sm + CH_OFF + b2 * 2048 + ((S ^ (b2 & 7)) << 4) + (c2 & 3) * 4)
            = h0[gb * UU + uu];
    }
    float cst = c0[gb * UU + u0 + c2];
    __syncthreads();

    // precompute DSMEM destinations for this thread's h element
    const uint32_t smbase = (uint32_t)__cvta_generic_to_shared(sm);
    uint32_t dst[CL];
    {
        int S2 = (int)rank * 8 + (c2 >> 2);
        uint32_t lofs = smbase + CH_OFF + (uint32_t)(b2 * 2048 +
                        ((S2 ^ (b2 & 7)) << 4) + (c2 & 3) * 4);
#pragma unroll
        for (int p = 0; p < CL; ++p)
            asm("mapa.shared::cluster.u32 %0, %1, %2;"
                : "=r"(dst[p]) : "r"(lofs), "r"(p));
    }

    // precomputed compute-phase pointers (j*128 folds into imm offsets)
    const char* hp[8];
#pragma unroll
    for (int b = 0; b < 8; ++b)
        hp[b] = sm + CH_OFF + b * 2048 + ((ks ^ b) << 4);
    const int ckey = c & 7;
    const char* wp0 = sm + (0 * 32 + c) * 2048 + ((ks ^ ckey) << 4);
    const char* wp1 = sm + (1 * 32 + c) * 2048 + ((ks ^ ckey) << 4);
    const char* wp2 = sm + (2 * 32 + c) * 2048 + ((ks ^ ckey) << 4);

    const size_t gstride = (size_t)TT * BB * UU;
    const float* xpi = &g_xp[0][0][0][0] + 0 * gstride + (size_t)gb * UU + u0 + c2;
    const float* xpf = &g_xp[0][0][0][0] + 1 * gstride + (size_t)gb * UU + u0 + c2;
    const float* xpc = &g_xp[0][0][0][0] + 2 * gstride + (size_t)gb * UU + u0 + c2;
    float* orow = out + (size_t)gb * TT * UU + u0 + c2;

    float pi = __ldcg(xpi), pf = __ldcg(xpf), pc = __ldcg(xpc);

    for (int t = 0; t < TT; ++t) {
        unsigned long long acc[8][3];
#pragma unroll
        for (int b = 0; b < 8; ++b)
#pragma unroll
            for (int g = 0; g < 3; ++g) acc[b][g] = 0ull;

#pragma unroll
        for (int j = 0; j < 16; ++j) {
            const ulonglong2 w0 = *(const ulonglong2*)(wp0 + j * 128);
            const ulonglong2 w1 = *(const ulonglong2*)(wp1 + j * 128);
            const ulonglong2 w2 = *(const ulonglong2*)(wp2 + j * 128);
#pragma unroll
            for (int b = 0; b < 8; ++b) {
                const ulonglong2 hv = *(const ulonglong2*)(hp[b] + j * 128);
                fma2(acc[b][0], hv.x, w0.x); fma2(acc[b][0], hv.y, w0.y);
                fma2(acc[b][1], hv.x, w1.x); fma2(acc[b][1], hv.y, w1.y);
                fma2(acc[b][2], hv.x, w2.x); fma2(acc[b][2], hv.y, w2.y);
            }
        }
        if (t < TT - 1)
            asm volatile("barrier.cluster.arrive.aligned;" ::: "memory"); // A

        // shfl-reduce over ks -> lanes ks==0
#pragma unroll
        for (int b = 0; b < 8; ++b) {
            float rr[3];
#pragma unroll
            for (int g = 0; g < 3; ++g) {
                float2 v = upk(acc[b][g]);
                float s = v.x + v.y;
                s += __shfl_xor_sync(0xffffffffu, s, 4);
                s += __shfl_xor_sync(0xffffffffu, s, 8);
                s += __shfl_xor_sync(0xffffffffu, s, 16);
                rr[g] = s;
            }
            if (ks == 0) {
                sred[(b * 3 + 0) * 32 + c] = rr[0];
                sred[(b * 3 + 1) * 32 + c] = rr[1];
                sred[(b * 3 + 2) * 32 + c] = rr[2];
            }
        }
        __syncthreads();

        float S0 = sred[(b2 * 3 + 0) * 32 + c2];
        float S1 = sred[(b2 * 3 + 1) * 32 + c2];
        float S2v = sred[(b2 * 3 + 2) * 32 + c2];
        float ig = fsig(pi + S0);
        float fg = fsig(pf + S1);
        float cin = ftanh(pc + S2v);
        cst = fg * cst + ig * cin;
        float hn = ftanh(cst);
        orow[(size_t)t * UU] = hn;

        if (t < TT - 1) {
            asm volatile("barrier.cluster.wait.aligned;" ::: "memory");   // A
#pragma unroll
            for (int p = 0; p < CL; ++p)
                asm volatile("st.shared::cluster.f32 [%0], %1;"
                             :: "r"(dst[p]), "f"(hn) : "memory");
            asm volatile("barrier.cluster.arrive.aligned;" ::: "memory"); // B
            pi = __ldcg(xpi + (size_t)(t + 1) * (BB * UU));
            pf = __ldcg(xpf + (size_t)(t + 1) * (BB * UU));
            pc = __ldcg(xpc + (size_t)(t + 1) * (BB * UU));
            asm volatile("barrier.cluster.wait.aligned;" ::: "memory");   // B
        }
    }
}

// ============================================================================
// FALLBACK: R10 persistent kernel (proven 3078 us), verbatim.
// ============================================================================
__global__ void __launch_bounds__(NTH, 1) lstm_fallback(
    const float* __restrict__ whi, const float* __restrict__ whf,
    const float* __restrict__ whc, const float* __restrict__ c0,
    float* __restrict__ out) {
    extern __shared__ __align__(16) char sm[];
    float* smW = (float*)(sm + W_OFF);
    float* smR = (float*)(sm + R_OFF);

    const int tid = threadIdx.x;
    const int wid = tid >> 5, lane = tid & 31;
    const int u0 = blockIdx.x * 4;
    const int c  = tid & 1;
    const int bg = (tid >> 1) & 7;
    const int ks = tid >> 4;
    const int rot = (ks & 1) * 2;
    const int lr = lane >> 3, ls = lane & 7;
    const int b2 = tid >> 2, c2 = tid & 3;
    const int u = u0 + c2;

    {
        const float* wsrc[3] = {whi, whf, whc};
        for (int i = tid; i < 3 * 4 * UU; i += NTH) {
            int cc = i & 3, k = (i >> 2) & 511, g = i >> 11;
            smW[(g * 4 + cc) * WROW + k] = wsrc[g][k * UU + u0 + cc];
        }
    }
    float cst = (tid < 256) ? c0[b2 * UU + u] : 0.0f;

    const uint32_t smbase = (uint32_t)__cvta_generic_to_shared(sm);
    const uint32_t flagaddr = smbase + FLAG_OFF;
    if (tid == 0) *(unsigned*)(sm + FLAG_OFF) = 0u;

    const int perm = bg * 2 + c;
    float* redw = smR + (bg * 8) * 4 * REDO + (c * 2) * REDO + (ks ^ perm);
    const float* redr = smR + tid * REDO;

    const size_t gstride = (size_t)TT * BB * UU;
    const float* xpi = &g_xp[0][0][0][0] + 0 * gstride + (size_t)b2 * UU + u;
    const float* xpf = &g_xp[0][0][0][0] + 1 * gstride + (size_t)b2 * UU + u;
    const float* xpc = &g_xp[0][0][0][0] + 2 * gstride + (size_t)b2 * UU + u;
    float* orow = out + (size_t)b2 * TT * UU + u;

    __syncthreads();

    for (int t = 0; t < TT; ++t) {
        if (tid < 256) {
            float pi = __ldcg(xpi + (size_t)t * (BB * UU));
            float pf = __ldcg(xpf + (size_t)t * (BB * UU));
            float pc = __ldcg(xpc + (size_t)t * (BB * UU));

            if (t > 0) {
                unsigned v;
                do {
                    asm volatile("ld.acquire.cta.shared.u32 %0, [%1];"
                                 : "=r"(v) : "r"(flagaddr) : "memory");
                } while (v < (unsigned)t);
            }

            const float* hsrc = &g_hbuf[(t + 1) & 1][0];
#pragma unroll
            for (int j = 0; j < 32; ++j) {
                int jr = j & 15, js = j >> 4;
                int r = jr * 4 + lr;
                int s = wid * 16 + js * 8 + ls;
                uint32_t dst = smbase + r * 2048 +
                               (uint32_t)((s ^ ((r >> 3) & 7)) << 4);
                cp16(dst, hsrc + r * 512 + s * 4);
            }
            asm volatile("cp.async.commit_group;");
            asm volatile("cp.async.wait_group 0;");
            __syncwarp();

            unsigned long long acc[8][3][2];
#pragma unroll
            for (int i = 0; i < 8; ++i)
#pragma unroll
                for (int g = 0; g < 3; ++g) {
                    acc[i][g][0] = 0ull; acc[i][g][1] = 0ull;
                }

#pragma unroll
            for (int j = 0; j < 8; ++j) {
                const int k4 = ks * 8 + ((j + rot) & 7);
                ulonglong2 wv[3][2];
#pragma unroll
                for (int g = 0; g < 3; ++g)
#pragma unroll
                    for (int q = 0; q < 2; ++q)
                        wv[g][q] = *(const ulonglong2*)(
                            smW + (g * 4 + c * 2 + q) * WROW + k4 * 4);
                const uint32_t koff = (uint32_t)((k4 ^ bg) << 4);
                const char* hb = sm + (bg * 8) * 2048 + koff;
#pragma unroll
                for (int i = 0; i < 8; ++i) {
                    const ulonglong2 hv = *(const ulonglong2*)(hb + i * 2048);
#pragma unroll
                    for (int g = 0; g < 3; ++g)
#pragma unroll
                        for (int q = 0; q < 2; ++q) {
                            fma2(acc[i][g][q], hv.x, wv[g][q].x);
                            fma2(acc[i][g][q], hv.y, wv[g][q].y);
                        }
                }
            }

#pragma unroll
            for (int i = 0; i < 8; ++i)
#pragma unroll
                for (int g = 0; g < 3; ++g)
#pragma unroll
                    for (int q = 0; q < 2; ++q) {
                        float2 v = upk(acc[i][g][q]);
                        redw[i * 4 * REDO + q * REDO + g * 16] = v.x + v.y;
                    }
            __syncthreads();

            float s[3];
#pragma unroll
            for (int g = 0; g < 3; ++g) {
                const float* rb = redr + g * 16;
                float4 a = *(const float4*)(rb + 0);
                float4 b = *(const float4*)(rb + 4);
                float4 d = *(const float4*)(rb + 8);
                float4 e = *(const float4*)(rb + 12);
                s[g] = (((a.x + a.y) + (a.z + a.w)) + ((b.x + b.y) + (b.z + b.w)))
                     + (((d.x + d.y) + (d.z + d.w)) + ((e.x + e.y) + (e.z + e.w)));
            }
            float ig = fsig(pi + s[0]);
            float fg = fsig(pf + s[1]);
            float cin = ftanh(pc + s[2]);
            cst = fg * cst + ig * cin;
            float hn = ftanh(cst);
            __stcg(&g_hbuf[t & 1][b2 * UU + u], hn);
            orow[(size_t)t * UU] = hn;

            if (t < TT - 1) {
                asm volatile("membar.cta;" ::: "memory");
                asm volatile("bar.arrive 1, %0;" :: "n"(NTH) : "memory");
            }
        } else {
            __syncthreads();
            if (t < TT - 1) {
                asm volatile("bar.sync 1, %0;" :: "n"(NTH) : "memory");
                if (lane == 0) {
                    asm volatile("red.release.gpu.global.add.u32 [%0], 1;"
                                 :: "l"(&g_count) : "memory");
                    unsigned target = (unsigned)(t + 1) * NCTA;
                    unsigned v;
                    do {
                        asm volatile("ld.acquire.gpu.u32 %0, [%1];"
                                     : "=r"(v) : "l"(&g_count) : "memory");
                    } while (v < target);
                    asm volatile("st.release.cta.shared.u32 [%0], %1;"
                                 :: "r"(flagaddr), "r"((unsigned)(t + 1))
                                 : "memory");
                }
                __syncwarp();
            }
        }
    }
}

extern "C" void kernel_launch(void* const* d_in, const int* in_sizes, int n_in,
                              void* d_out, int out_size) {
    const float* x   = (const float*)d_in[0];
    const float* wxi = (const float*)d_in[1];
    const float* wxf = (const float*)d_in[2];
    const float* wxc = (const float*)d_in[3];
    const float* whi = (const float*)d_in[4];
    const float* whf = (const float*)d_in[5];
    const float* whc = (const float*)d_in[6];
    const float* bi  = (const float*)d_in[7];
    const float* bf  = (const float*)d_in[8];
    const float* bc  = (const float*)d_in[9];
    const float* h0  = (const float*)d_in[10];
    const float* c0  = (const float*)d_in[11];
    float* out = (float*)d_out;

    proj_kernel<<<dim3(8, TT), 256>>>(x, wxi, wxf, wxc, bi, bf, bc);
    init_kernel<<<(BB * UU + 255) / 256, 256>>>(h0);

    // capability probe (host-side, deterministic every call)
    cudaError_t e1 = cudaFuncSetAttribute(
        lstm_cluster, cudaFuncAttributeNonPortableClusterSizeAllowed, 1);
    cudaError_t e2 = cudaFuncSetAttribute(
        lstm_cluster, cudaFuncAttributeMaxDynamicSharedMemorySize, CSM_TOTAL);
    if (e1 == cudaSuccess && e2 == cudaSuccess) {
        cudaLaunchConfig_t cfg = {};
        cfg.gridDim = dim3(NCTA, 1, 1);
        cfg.blockDim = dim3(256, 1, 1);
        cfg.dynamicSmemBytes = CSM_TOTAL;
        cudaLaunchAttribute at[1];
        at[0].id = cudaLaunchAttributeClusterDimension;
        at[0].val.clusterDim.x = CL;
        at[0].val.clusterDim.y = 1;
        at[0].val.clusterDim.z = 1;
        cfg.attrs = at;
        cfg.numAttrs = 1;
        int mc = 0;
        cudaError_t e3 = cudaOccupancyMaxActiveClusters(&mc, lstm_cluster, &cfg);
        if (e3 == cudaSuccess && mc >= NCTA / CL) {
            cudaLaunchKernelEx(&cfg, lstm_cluster, whi, whf, whc, h0, c0, out);
            return;
        }
    }
    (void)cudaGetLastError();
    cudaFuncSetAttribute(lstm_fallback,
                         cudaFuncAttributeMaxDynamicSharedMemorySize, SM_TOTAL);
    lstm_fallback<<<NCTA, NTH, SM_TOTAL>>>(whi, whf, whc, c0, out);
}